// round 9
// baseline (speedup 1.0000x reference)
#include <cuda_runtime.h>
#include <cuda_bf16.h>

// Problem constants (fixed by the reference setup_inputs)
#define BB 2
#define NN 8192
#define MM 32768
#define SS 4096
#define NQ (BB * SS)          // 8192 queries
#define NT (BB * MM)          // 65536 targets

// Spatial grid: 32^3 cells per batch over [-4.8, 4.8], h = 0.3
#define G 32
#define GLO (-4.8f)
#define GH 0.3f
#define GINVH 3.33333333f
#define CELLS_PER_B (G * G * G)       // 32768
#define NC (BB * CELLS_PER_B)         // 65536

// Single fused kernel: 148 blocks (one per SM, wave-1 co-resident) x 256 threads
#define NBLK 148
#define TPB 256
#define NTHREADS (NBLK * TPB)
#define WPB (TPB / 32)
#define NWARP (NBLK * WPB)

// Scan decomposition inside the fused kernel
#define SCB 64
#define CPB (NC / SCB)                 // 1024 cells per scan block
#define CPT (CPB / TPB)                // 4 cells per thread

// Device scratch (no allocations allowed). All counters self-restore each call.
__device__ float4 g_target4[NT];     // (x, y, z, cell-id-as-int-bits)
__device__ float4 g_tsorted[NT];     // cell-sorted targets
__device__ float4 g_pred4[NQ];       // gathered query points
__device__ int    g_count[NC];
__device__ int    g_cellstart[NC + 1];
__device__ int    g_bsum[SCB];
__device__ int    g_boff[SCB];
__device__ int           g_bar_count;       // resets to 0 at every barrier
__device__ volatile int  g_bar_gen;         // monotonic across barriers/replays

__device__ __forceinline__ void grid_barrier() {
    __syncthreads();
    if (threadIdx.x == 0) {
        __threadfence();
        int gen = g_bar_gen;
        int arrived = atomicAdd(&g_bar_count, 1);
        if (arrived == NBLK - 1) {
            g_bar_count = 0;
            __threadfence();
            g_bar_gen = gen + 1;
        } else {
            while (g_bar_gen == gen) { }
        }
        __threadfence();
    }
    __syncthreads();
}

__device__ __forceinline__ int cell_coord(float v) {
    int c = (int)((v - GLO) * GINVH);
    return min(max(c, 0), G - 1);
}

// idx is int32 on device (JAX x64-disabled coerces int64 -> int32).
__global__ void __launch_bounds__(TPB) fused_chamfer_kernel(
    const float* __restrict__ target,
    const float* __restrict__ pred,
    const int* __restrict__ idx,
    float* __restrict__ out
) {
    __shared__ int   iw[WPB];
    __shared__ float fw[WPB];

    const int tid = blockIdx.x * TPB + threadIdx.x;
    const int lane = threadIdx.x & 31;
    const int wid = threadIdx.x >> 5;

    // ---- Phase 0: zero counts + output, gather query points ----
    for (int i = tid; i < NC; i += NTHREADS) g_count[i] = 0;
    for (int i = tid; i < NQ; i += NTHREADS) {
        int b = i / SS;
        int s = i % SS;
        int j = min(max(idx[s], 0), NN - 1);
        const float* p = pred + ((long long)b * NN + j) * 3;
        g_pred4[i] = make_float4(p[0], p[1], p[2], 0.0f);
    }
    if (tid == 0) out[0] = 0.0f;
    grid_barrier();

    // ---- Phase 1: histogram targets into cells ----
    for (int i = tid; i < NT; i += NTHREADS) {
        float x = target[3 * i + 0];
        float y = target[3 * i + 1];
        float z = target[3 * i + 2];
        int b = i / MM;
        int cell = b * CELLS_PER_B +
                   ((cell_coord(z) * G + cell_coord(y)) * G + cell_coord(x));
        g_target4[i] = make_float4(x, y, z, __int_as_float(cell));
        atomicAdd(&g_count[cell], 1);
    }
    grid_barrier();

    // ---- Phase 2a: per-scan-block totals (blocks 0..63) ----
    if (blockIdx.x < SCB) {
        int base = blockIdx.x * CPB + threadIdx.x * CPT;
        int s = 0;
#pragma unroll
        for (int k = 0; k < CPT; k++) s += g_count[base + k];
#pragma unroll
        for (int o = 16; o > 0; o >>= 1) s += __shfl_down_sync(0xFFFFFFFFu, s, o);
        if (lane == 0) iw[wid] = s;
        __syncthreads();
        if (threadIdx.x == 0) {
            int t = 0;
#pragma unroll
            for (int w = 0; w < WPB; w++) t += iw[w];
            g_bsum[blockIdx.x] = t;
        }
    }
    grid_barrier();

    // ---- Phase 2b: warp 0 of block 0 scans the 64 block sums -> g_boff ----
    if (blockIdx.x == 0 && threadIdx.x < 32) {
        int w0 = g_bsum[lane];
        int w1 = g_bsum[lane + 32];
        int i0 = w0, i1 = w1;
#pragma unroll
        for (int o = 1; o < 32; o <<= 1) {
            int t0 = __shfl_up_sync(0xFFFFFFFFu, i0, o);
            int t1 = __shfl_up_sync(0xFFFFFFFFu, i1, o);
            if (lane >= o) { i0 += t0; i1 += t1; }
        }
        int tot0 = __shfl_sync(0xFFFFFFFFu, i0, 31);
        g_boff[lane] = i0 - w0;
        g_boff[lane + 32] = tot0 + i1 - w1;
    }
    grid_barrier();

    // ---- Phase 2c: local exclusive scan + global offset -> g_cellstart ----
    if (blockIdx.x < SCB) {
        int base = blockIdx.x * CPB + threadIdx.x * CPT;
        int c[CPT];
        int tsum = 0;
#pragma unroll
        for (int k = 0; k < CPT; k++) { c[k] = g_count[base + k]; tsum += c[k]; }
        int incl = tsum;
#pragma unroll
        for (int o = 1; o < 32; o <<= 1) {
            int t = __shfl_up_sync(0xFFFFFFFFu, incl, o);
            if (lane >= o) incl += t;
        }
        if (lane == 31) iw[wid] = incl;
        __syncthreads();
        if (wid == 0) {
            int w = (lane < WPB) ? iw[lane] : 0;
#pragma unroll
            for (int o = 1; o < 32; o <<= 1) {
                int t = __shfl_up_sync(0xFFFFFFFFu, w, o);
                if (lane >= o) w += t;
            }
            if (lane < WPB) iw[lane] = w;
        }
        __syncthreads();
        int run = g_boff[blockIdx.x] + incl - tsum + (wid > 0 ? iw[wid - 1] : 0);
#pragma unroll
        for (int k = 0; k < CPT; k++) { g_cellstart[base + k] = run; run += c[k]; }
    }
    if (tid == 0) g_cellstart[NC] = NT;
    grid_barrier();

    // ---- Phase 3: scatter into sorted order (consumes g_count back to 0) ----
    for (int i = tid; i < NT; i += NTHREADS) {
        float4 t = g_target4[i];
        int cell = __float_as_int(t.w);
        int old = atomicAdd(&g_count[cell], -1);     // old in [1..count]
        g_tsorted[g_cellstart[cell] + old - 1] = t;
    }
    grid_barrier();

    // ---- Phase 4: warp-per-query expanding-box exact NN + fused mean ----
    const int gw = blockIdx.x * WPB + wid;
    const float INF = __int_as_float(0x7F800000);
    float acc = 0.0f;

    for (int q = gw; q < NQ; q += NWARP) {
        float4 qp = g_pred4[q];
        const float qx = qp.x, qy = qp.y, qz = qp.z;
        const int hx = cell_coord(qx);
        const int hy = cell_coord(qy);
        const int hz = cell_coord(qz);
        const int cbase = (q / SS) * CELLS_PER_B;

        float wbest = INF;
        for (int r = 1; r < G; r++) {
            const int x0 = max(hx - r, 0), x1 = min(hx + r, G - 1);
            const int y0 = max(hy - r, 0), y1 = min(hy + r, G - 1);
            const int z0 = max(hz - r, 0), z1 = min(hz + r, G - 1);
            float lbest = INF;
            for (int cz = z0; cz <= z1; cz++) {
                for (int cy = y0; cy <= y1; cy++) {
                    int rowbase = cbase + (cz * G + cy) * G;
                    int s0 = g_cellstart[rowbase + x0];
                    int e0 = g_cellstart[rowbase + x1 + 1];
                    for (int i = s0 + lane; i < e0; i += 32) {
                        float4 t = g_tsorted[i];
                        float dx = qx - t.x;
                        float dy = qy - t.y;
                        float dz = qz - t.z;
                        float d2 = fmaf(dx, dx, fmaf(dy, dy, dz * dz));
                        lbest = fminf(lbest, d2);
                    }
                }
            }
            float wm = lbest;
#pragma unroll
            for (int o = 16; o > 0; o >>= 1)
                wm = fminf(wm, __shfl_xor_sync(0xFFFFFFFFu, wm, o));
            wbest = wm;

            // Exact stop: all unscanned points lie outside the box's real-space
            // extent (clamped edge cells are open -> +inf margin on that face).
            float m = INF;
            if (x0 > 0)     m = fminf(m, qx - (GLO + (float)x0 * GH));
            if (x1 < G - 1) m = fminf(m, (GLO + (float)(x1 + 1) * GH) - qx);
            if (y0 > 0)     m = fminf(m, qy - (GLO + (float)y0 * GH));
            if (y1 < G - 1) m = fminf(m, (GLO + (float)(y1 + 1) * GH) - qy);
            if (z0 > 0)     m = fminf(m, qz - (GLO + (float)z0 * GH));
            if (z1 < G - 1) m = fminf(m, (GLO + (float)(z1 + 1) * GH) - qz);
            m = fmaxf(m, 0.0f);
            if (wbest <= m * m) break;
            if (x0 == 0 && y0 == 0 && z0 == 0 &&
                x1 == G - 1 && y1 == G - 1 && z1 == G - 1) break;
        }
        if (lane == 0) acc += sqrtf(fmaxf(wbest, 0.0f));
    }

    // Block-level sum of per-warp accumulators, then one atomicAdd per block.
    if (lane == 0) fw[wid] = acc;
    __syncthreads();
    if (threadIdx.x == 0) {
        float s = 0.0f;
#pragma unroll
        for (int w = 0; w < WPB; w++) s += fw[w];
        atomicAdd(out, s * (1.0f / (float)NQ));
    }
}

extern "C" void kernel_launch(void* const* d_in, const int* in_sizes, int n_in,
                              void* d_out, int out_size) {
    const float* pred = (const float*)d_in[0];
    const float* target = (const float*)d_in[1];
    const int* idx = (const int*)d_in[2];
    float* out = (float*)d_out;

    fused_chamfer_kernel<<<NBLK, TPB>>>(target, pred, idx, out);
}

// round 10
// speedup vs baseline: 1.1401x; 1.1401x over previous
#include <cuda_runtime.h>
#include <cuda_bf16.h>

// Problem constants (fixed by the reference setup_inputs)
#define BB 2
#define NN 8192
#define MM 32768
#define SS 4096
#define NQ (BB * SS)          // 8192 queries
#define NT (BB * MM)          // 65536 targets

// Spatial grid: 32^3 cells per batch over [-4.8, 4.8], h = 0.3
#define G 32
#define GLO (-4.8f)
#define GH 0.3f
#define GINVH 3.33333333f
#define CELLS_PER_B (G * G * G)       // 32768
#define NC (BB * CELLS_PER_B)         // 65536

// Single fused kernel: 148 blocks (one per SM, co-resident) x 1024 threads
#define NBLK 148
#define TPB 1024
#define NTHREADS (NBLK * TPB)
#define WPB (TPB / 32)                 // 32 warps per block

// Scan decomposition: 64 scan-blocks x 1024 cells (1 cell per thread)
#define SCB 64
#define CPB (NC / SCB)                 // 1024

#define QCHUNK 2                       // queries stolen per warp grab

// Device scratch (no allocations allowed). All counters self-restore each call.
__device__ float4 g_target4[NT];     // (x, y, z, cell-id-as-int-bits)
__device__ float4 g_tsorted[NT];     // cell-sorted targets
__device__ float4 g_pred4[NQ];       // gathered query points
__device__ int    g_count[NC];
__device__ int    g_cellstart[NC + 1];
__device__ int    g_bsum[SCB];
__device__ int    g_boff[SCB];
__device__ int    g_qnext;                  // work-steal cursor (reset per launch)
__device__ int           g_bar_count;       // resets to 0 at every barrier
__device__ volatile int  g_bar_gen;         // monotonic across barriers/replays

__device__ __forceinline__ void grid_barrier() {
    __syncthreads();
    if (threadIdx.x == 0) {
        __threadfence();
        int gen = g_bar_gen;
        int arrived = atomicAdd(&g_bar_count, 1);
        if (arrived == NBLK - 1) {
            g_bar_count = 0;
            __threadfence();
            g_bar_gen = gen + 1;
        } else {
            while (g_bar_gen == gen) { }
        }
        __threadfence();
    }
    __syncthreads();
}

__device__ __forceinline__ int cell_coord(float v) {
    int c = (int)((v - GLO) * GINVH);
    return min(max(c, 0), G - 1);
}

// idx is int32 on device (JAX x64-disabled coerces int64 -> int32).
__global__ void __launch_bounds__(TPB) fused_chamfer_kernel(
    const float* __restrict__ target,
    const float* __restrict__ pred,
    const int* __restrict__ idx,
    float* __restrict__ out
) {
    __shared__ int   iw[WPB];
    __shared__ float fw[WPB];

    const int tid = blockIdx.x * TPB + threadIdx.x;
    const int lane = threadIdx.x & 31;
    const int wid = threadIdx.x >> 5;

    // ---- Phase 0: zero counts/out/cursor, gather query points ----
    if (tid < NC) g_count[tid] = 0;
    if (tid < NQ) {
        int b = tid / SS;
        int s = tid % SS;
        int j = min(max(idx[s], 0), NN - 1);
        const float* p = pred + ((long long)b * NN + j) * 3;
        g_pred4[tid] = make_float4(p[0], p[1], p[2], 0.0f);
    }
    if (tid == 0) { out[0] = 0.0f; g_qnext = 0; }
    grid_barrier();

    // ---- Phase 1: histogram targets into cells ----
    if (tid < NT) {
        int i = tid;
        float x = target[3 * i + 0];
        float y = target[3 * i + 1];
        float z = target[3 * i + 2];
        int b = i / MM;
        int cell = b * CELLS_PER_B +
                   ((cell_coord(z) * G + cell_coord(y)) * G + cell_coord(x));
        g_target4[i] = make_float4(x, y, z, __int_as_float(cell));
        atomicAdd(&g_count[cell], 1);
    }
    grid_barrier();

    // ---- Phase 2a: per-scan-block totals (blocks 0..63, 1 cell/thread) ----
    if (blockIdx.x < SCB) {
        int s = g_count[blockIdx.x * CPB + threadIdx.x];
#pragma unroll
        for (int o = 16; o > 0; o >>= 1) s += __shfl_down_sync(0xFFFFFFFFu, s, o);
        if (lane == 0) iw[wid] = s;
        __syncthreads();
        if (threadIdx.x == 0) {
            int t = 0;
#pragma unroll
            for (int w = 0; w < WPB; w++) t += iw[w];
            g_bsum[blockIdx.x] = t;
        }
    }
    grid_barrier();

    // ---- Phase 2b: warp 0 of block 0 scans the 64 block sums -> g_boff ----
    if (blockIdx.x == 0 && threadIdx.x < 32) {
        int w0 = g_bsum[lane];
        int w1 = g_bsum[lane + 32];
        int i0 = w0, i1 = w1;
#pragma unroll
        for (int o = 1; o < 32; o <<= 1) {
            int t0 = __shfl_up_sync(0xFFFFFFFFu, i0, o);
            int t1 = __shfl_up_sync(0xFFFFFFFFu, i1, o);
            if (lane >= o) { i0 += t0; i1 += t1; }
        }
        int tot0 = __shfl_sync(0xFFFFFFFFu, i0, 31);
        g_boff[lane] = i0 - w0;
        g_boff[lane + 32] = tot0 + i1 - w1;
    }
    grid_barrier();

    // ---- Phase 2c: block-local exclusive scan + offset -> g_cellstart ----
    if (blockIdx.x < SCB) {
        int c = g_count[blockIdx.x * CPB + threadIdx.x];
        int incl = c;
#pragma unroll
        for (int o = 1; o < 32; o <<= 1) {
            int t = __shfl_up_sync(0xFFFFFFFFu, incl, o);
            if (lane >= o) incl += t;
        }
        if (lane == 31) iw[wid] = incl;
        __syncthreads();
        if (wid == 0) {
            int w = iw[lane];                  // WPB == 32: all lanes valid
#pragma unroll
            for (int o = 1; o < 32; o <<= 1) {
                int t = __shfl_up_sync(0xFFFFFFFFu, w, o);
                if (lane >= o) w += t;
            }
            iw[lane] = w;
        }
        __syncthreads();
        int pre = g_boff[blockIdx.x] + incl - c + (wid > 0 ? iw[wid - 1] : 0);
        g_cellstart[blockIdx.x * CPB + threadIdx.x] = pre;
    }
    if (tid == 0) g_cellstart[NC] = NT;
    grid_barrier();

    // ---- Phase 3: scatter into sorted order (consumes g_count back to 0) ----
    if (tid < NT) {
        float4 t = g_target4[tid];
        int cell = __float_as_int(t.w);
        int old = atomicAdd(&g_count[cell], -1);     // old in [1..count]
        g_tsorted[g_cellstart[cell] + old - 1] = t;
    }
    grid_barrier();

    // ---- Phase 4: warp-per-query NN (work stealing, incremental rings) ----
    const float INF = __int_as_float(0x7F800000);
    float acc = 0.0f;

    for (;;) {
        int base;
        if (lane == 0) base = atomicAdd(&g_qnext, QCHUNK);
        base = __shfl_sync(0xFFFFFFFFu, base, 0);
        if (base >= NQ) break;

        int qend = min(base + QCHUNK, NQ);
        for (int q = base; q < qend; q++) {
            float4 qp = g_pred4[q];
            const float qx = qp.x, qy = qp.y, qz = qp.z;
            const int hx = cell_coord(qx);
            const int hy = cell_coord(qy);
            const int hz = cell_coord(qz);
            const int cbase = (q / SS) * CELLS_PER_B;

            float lbest = INF;
            float wbest = INF;
            // previous box (empty initially)
            int px0 = 1, px1 = 0, py0 = 1, py1 = 0, pz0 = 1, pz1 = 0;

            for (int r = 1; r < G; r++) {
                const int x0 = max(hx - r, 0), x1 = min(hx + r, G - 1);
                const int y0 = max(hy - r, 0), y1 = min(hy + r, G - 1);
                const int z0 = max(hz - r, 0), z1 = min(hz + r, G - 1);

                for (int cz = z0; cz <= z1; cz++) {
                    const bool zin = (cz >= pz0 && cz <= pz1);
                    for (int cy = y0; cy <= y1; cy++) {
                        const int rowbase = cbase + (cz * G + cy) * G;
                        const bool in_prev = zin && cy >= py0 && cy <= py1;
                        int sa, sb, sc, sd;     // up to two segments
                        if (!in_prev) {
                            sa = x0; sb = x1; sc = 1; sd = 0;
                        } else {
                            sa = x0; sb = px0 - 1;      // left sliver (may be empty)
                            sc = px1 + 1; sd = x1;      // right sliver (may be empty)
                        }
                        if (sa <= sb) {
                            int s0 = g_cellstart[rowbase + sa];
                            int e0 = g_cellstart[rowbase + sb + 1];
                            for (int i = s0 + lane; i < e0; i += 32) {
                                float4 t = g_tsorted[i];
                                float dx = qx - t.x;
                                float dy = qy - t.y;
                                float dz = qz - t.z;
                                float d2 = fmaf(dx, dx, fmaf(dy, dy, dz * dz));
                                lbest = fminf(lbest, d2);
                            }
                        }
                        if (sc <= sd) {
                            int s0 = g_cellstart[rowbase + sc];
                            int e0 = g_cellstart[rowbase + sd + 1];
                            for (int i = s0 + lane; i < e0; i += 32) {
                                float4 t = g_tsorted[i];
                                float dx = qx - t.x;
                                float dy = qy - t.y;
                                float dz = qz - t.z;
                                float d2 = fmaf(dx, dx, fmaf(dy, dy, dz * dz));
                                lbest = fminf(lbest, d2);
                            }
                        }
                    }
                }

                float wm = lbest;
#pragma unroll
                for (int o = 16; o > 0; o >>= 1)
                    wm = fminf(wm, __shfl_xor_sync(0xFFFFFFFFu, wm, o));
                wbest = wm;

                // Exact stop: all unscanned points lie outside the box's
                // real-space extent (clamped edge cells are open -> +inf).
                float m = INF;
                if (x0 > 0)     m = fminf(m, qx - (GLO + (float)x0 * GH));
                if (x1 < G - 1) m = fminf(m, (GLO + (float)(x1 + 1) * GH) - qx);
                if (y0 > 0)     m = fminf(m, qy - (GLO + (float)y0 * GH));
                if (y1 < G - 1) m = fminf(m, (GLO + (float)(y1 + 1) * GH) - qy);
                if (z0 > 0)     m = fminf(m, qz - (GLO + (float)z0 * GH));
                if (z1 < G - 1) m = fminf(m, (GLO + (float)(z1 + 1) * GH) - qz);
                m = fmaxf(m, 0.0f);
                if (wbest <= m * m) break;
                if (x0 == 0 && y0 == 0 && z0 == 0 &&
                    x1 == G - 1 && y1 == G - 1 && z1 == G - 1) break;

                px0 = x0; px1 = x1; py0 = y0; py1 = y1; pz0 = z0; pz1 = z1;
            }
            if (lane == 0) acc += sqrtf(fmaxf(wbest, 0.0f));
        }
    }

    // Block-level sum of per-warp accumulators, then one atomicAdd per block.
    if (lane == 0) fw[wid] = acc;
    __syncthreads();
    if (threadIdx.x == 0) {
        float s = 0.0f;
#pragma unroll
        for (int w = 0; w < WPB; w++) s += fw[w];
        atomicAdd(out, s * (1.0f / (float)NQ));
    }
}

extern "C" void kernel_launch(void* const* d_in, const int* in_sizes, int n_in,
                              void* d_out, int out_size) {
    const float* pred = (const float*)d_in[0];
    const float* target = (const float*)d_in[1];
    const int* idx = (const int*)d_in[2];
    float* out = (float*)d_out;

    fused_chamfer_kernel<<<NBLK, TPB>>>(target, pred, idx, out);
}

// round 11
// speedup vs baseline: 1.2602x; 1.1054x over previous
#include <cuda_runtime.h>
#include <cuda_bf16.h>

// Problem constants (fixed by the reference setup_inputs)
#define BB 2
#define NN 8192
#define MM 32768
#define SS 4096
#define NQ (BB * SS)          // 8192 queries
#define NT (BB * MM)          // 65536 targets

// Spatial grid: 32^3 cells per batch over [-4.8, 4.8], h = 0.3
#define G 32
#define GLO (-4.8f)
#define GH 0.3f
#define GINVH 3.33333333f
#define CELLS_PER_B (G * G * G)       // 32768
#define NC (BB * CELLS_PER_B)         // 65536

// Single fused kernel: 148 blocks (one per SM, co-resident) x 1024 threads
#define NBLK 148
#define TPB 1024
#define NTHREADS (NBLK * TPB)
#define WPB (TPB / 32)                 // 32 warps per block

// Scan decomposition: 64 scan-blocks x 1024 cells (1 cell per thread)
#define SCB 64
#define CPB (NC / SCB)                 // 1024

#define QCHUNK 2                       // queries stolen per warp grab
#define FULL 0xFFFFFFFFu

// Device scratch (no allocations allowed). All counters self-restore each call.
__device__ float4 g_target4[NT];     // (x, y, z, cell-id-as-int-bits)
__device__ float4 g_tsorted[NT];     // cell-sorted targets
__device__ float4 g_pred4[NQ];       // gathered query points
__device__ int    g_count[NC];
__device__ int    g_cellstart[NC + 1];
__device__ int    g_bsum[SCB];
__device__ int    g_boff[SCB];
__device__ int    g_qnext;                  // work-steal cursor (reset per launch)
__device__ int           g_bar_count;       // resets to 0 at every barrier
__device__ volatile int  g_bar_gen;         // monotonic across barriers/replays

__device__ __forceinline__ void grid_barrier() {
    __syncthreads();
    if (threadIdx.x == 0) {
        __threadfence();
        int gen = g_bar_gen;
        int arrived = atomicAdd(&g_bar_count, 1);
        if (arrived == NBLK - 1) {
            g_bar_count = 0;
            __threadfence();
            g_bar_gen = gen + 1;
        } else {
            while (g_bar_gen == gen) { }
        }
        __threadfence();
    }
    __syncthreads();
}

__device__ __forceinline__ int cell_coord(float v) {
    int c = (int)((v - GLO) * GINVH);
    return min(max(c, 0), G - 1);
}

// idx is int32 on device (JAX x64-disabled coerces int64 -> int32).
__global__ void __launch_bounds__(TPB) fused_chamfer_kernel(
    const float* __restrict__ target,
    const float* __restrict__ pred,
    const int* __restrict__ idx,
    float* __restrict__ out
) {
    __shared__ int   iw[WPB];
    __shared__ float fw[WPB];

    const int tid = blockIdx.x * TPB + threadIdx.x;
    const int lane = threadIdx.x & 31;
    const int wid = threadIdx.x >> 5;

    // ---- Phase 0: zero counts/out/cursor, gather query points ----
    if (tid < NC) g_count[tid] = 0;
    if (tid < NQ) {
        int b = tid / SS;
        int s = tid % SS;
        int j = min(max(idx[s], 0), NN - 1);
        const float* p = pred + ((long long)b * NN + j) * 3;
        g_pred4[tid] = make_float4(p[0], p[1], p[2], 0.0f);
    }
    if (tid == 0) { out[0] = 0.0f; g_qnext = 0; }
    grid_barrier();

    // ---- Phase 1: histogram targets into cells ----
    if (tid < NT) {
        int i = tid;
        float x = target[3 * i + 0];
        float y = target[3 * i + 1];
        float z = target[3 * i + 2];
        int b = i / MM;
        int cell = b * CELLS_PER_B +
                   ((cell_coord(z) * G + cell_coord(y)) * G + cell_coord(x));
        g_target4[i] = make_float4(x, y, z, __int_as_float(cell));
        atomicAdd(&g_count[cell], 1);
    }
    grid_barrier();

    // ---- Phase 2a: per-scan-block totals (blocks 0..63, 1 cell/thread) ----
    if (blockIdx.x < SCB) {
        int s = g_count[blockIdx.x * CPB + threadIdx.x];
#pragma unroll
        for (int o = 16; o > 0; o >>= 1) s += __shfl_down_sync(FULL, s, o);
        if (lane == 0) iw[wid] = s;
        __syncthreads();
        if (threadIdx.x == 0) {
            int t = 0;
#pragma unroll
            for (int w = 0; w < WPB; w++) t += iw[w];
            g_bsum[blockIdx.x] = t;
        }
    }
    grid_barrier();

    // ---- Phase 2b: warp 0 of block 0 scans the 64 block sums -> g_boff ----
    if (blockIdx.x == 0 && threadIdx.x < 32) {
        int w0 = g_bsum[lane];
        int w1 = g_bsum[lane + 32];
        int i0 = w0, i1 = w1;
#pragma unroll
        for (int o = 1; o < 32; o <<= 1) {
            int t0 = __shfl_up_sync(FULL, i0, o);
            int t1 = __shfl_up_sync(FULL, i1, o);
            if (lane >= o) { i0 += t0; i1 += t1; }
        }
        int tot0 = __shfl_sync(FULL, i0, 31);
        g_boff[lane] = i0 - w0;
        g_boff[lane + 32] = tot0 + i1 - w1;
    }
    grid_barrier();

    // ---- Phase 2c: block-local exclusive scan + offset -> g_cellstart ----
    if (blockIdx.x < SCB) {
        int c = g_count[blockIdx.x * CPB + threadIdx.x];
        int incl = c;
#pragma unroll
        for (int o = 1; o < 32; o <<= 1) {
            int t = __shfl_up_sync(FULL, incl, o);
            if (lane >= o) incl += t;
        }
        if (lane == 31) iw[wid] = incl;
        __syncthreads();
        if (wid == 0) {
            int w = iw[lane];                  // WPB == 32: all lanes valid
#pragma unroll
            for (int o = 1; o < 32; o <<= 1) {
                int t = __shfl_up_sync(FULL, w, o);
                if (lane >= o) w += t;
            }
            iw[lane] = w;
        }
        __syncthreads();
        int pre = g_boff[blockIdx.x] + incl - c + (wid > 0 ? iw[wid - 1] : 0);
        g_cellstart[blockIdx.x * CPB + threadIdx.x] = pre;
    }
    if (tid == 0) g_cellstart[NC] = NT;
    grid_barrier();

    // ---- Phase 3: scatter into sorted order (consumes g_count back to 0) ----
    if (tid < NT) {
        float4 t = g_target4[tid];
        int cell = __float_as_int(t.w);
        int old = atomicAdd(&g_count[cell], -1);     // old in [1..count]
        g_tsorted[g_cellstart[cell] + old - 1] = t;
    }
    grid_barrier();

    // ---- Phase 4: warp-per-query NN. Fast path: flattened 27-cell (r=1)
    //      scan with one parallel bound-fetch round trip + MLP point loop.
    //      Rare escalation: incremental ring expansion from r=2. ----
    const float INF = __int_as_float(0x7F800000);
    float acc = 0.0f;

    for (;;) {
        int base;
        if (lane == 0) base = atomicAdd(&g_qnext, QCHUNK);
        base = __shfl_sync(FULL, base, 0);
        if (base >= NQ) break;

        int qend = min(base + QCHUNK, NQ);
        for (int q = base; q < qend; q++) {
            float4 qp = g_pred4[q];
            const float qx = qp.x, qy = qp.y, qz = qp.z;
            const int hx = cell_coord(qx);
            const int hy = cell_coord(qy);
            const int hz = cell_coord(qz);
            const int cbase = (q / SS) * CELLS_PER_B;

            const int x0 = max(hx - 1, 0), x1 = min(hx + 1, G - 1);
            const int y0 = max(hy - 1, 0), y1 = min(hy + 1, G - 1);
            const int z0 = max(hz - 1, 0), z1 = min(hz + 1, G - 1);

            // Lanes 0-8: row starts; lanes 9-17: row ends. One round trip.
            int v = 0;
            {
                int i = (lane < 9) ? lane : lane - 9;
                if (lane < 18) {
                    int cz = hz + i / 3 - 1;
                    int cy = hy + i % 3 - 1;
                    if ((unsigned)cz < G && (unsigned)cy < G) {
                        int rowbase = cbase + (cz * G + cy) * G;
                        v = (lane < 9) ? g_cellstart[rowbase + x0]
                                       : g_cellstart[rowbase + x1 + 1];
                    }
                }
            }
            // Broadcast bounds; build prefix thresholds P1..P8, total, and
            // per-row address bases D_i = S_i - P_i (all warp-uniform regs).
            int S0 = __shfl_sync(FULL, v, 0), E0 = __shfl_sync(FULL, v, 9);
            int S1 = __shfl_sync(FULL, v, 1), E1 = __shfl_sync(FULL, v, 10);
            int S2 = __shfl_sync(FULL, v, 2), E2 = __shfl_sync(FULL, v, 11);
            int S3 = __shfl_sync(FULL, v, 3), E3 = __shfl_sync(FULL, v, 12);
            int S4 = __shfl_sync(FULL, v, 4), E4 = __shfl_sync(FULL, v, 13);
            int S5 = __shfl_sync(FULL, v, 5), E5 = __shfl_sync(FULL, v, 14);
            int S6 = __shfl_sync(FULL, v, 6), E6 = __shfl_sync(FULL, v, 15);
            int S7 = __shfl_sync(FULL, v, 7), E7 = __shfl_sync(FULL, v, 16);
            int S8 = __shfl_sync(FULL, v, 8), E8 = __shfl_sync(FULL, v, 17);
            int P1 = (E0 - S0);
            int P2 = P1 + (E1 - S1);
            int P3 = P2 + (E2 - S2);
            int P4 = P3 + (E3 - S3);
            int P5 = P4 + (E4 - S4);
            int P6 = P5 + (E5 - S5);
            int P7 = P6 + (E6 - S6);
            int P8 = P7 + (E7 - S7);
            int total = P8 + (E8 - S8);
            int D0 = S0;
            int D1 = S1 - P1;
            int D2 = S2 - P2;
            int D3 = S3 - P3;
            int D4 = S4 - P4;
            int D5 = S5 - P5;
            int D6 = S6 - P6;
            int D7 = S7 - P7;
            int D8 = S8 - P8;

            float lbest = INF;
#pragma unroll 4
            for (int t = lane; t < total; t += 32) {
                int d = D0;
                if (t >= P1) d = D1;
                if (t >= P2) d = D2;
                if (t >= P3) d = D3;
                if (t >= P4) d = D4;
                if (t >= P5) d = D5;
                if (t >= P6) d = D6;
                if (t >= P7) d = D7;
                if (t >= P8) d = D8;
                float4 tp = g_tsorted[d + t];
                float ddx = qx - tp.x;
                float ddy = qy - tp.y;
                float ddz = qz - tp.z;
                float d2 = fmaf(ddx, ddx, fmaf(ddy, ddy, ddz * ddz));
                lbest = fminf(lbest, d2);
            }
            float wbest = lbest;
#pragma unroll
            for (int o = 16; o > 0; o >>= 1)
                wbest = fminf(wbest, __shfl_xor_sync(FULL, wbest, o));

            // Exact stop bound for the r=1 box (clamped edges are open).
            float m = INF;
            if (x0 > 0)     m = fminf(m, qx - (GLO + (float)x0 * GH));
            if (x1 < G - 1) m = fminf(m, (GLO + (float)(x1 + 1) * GH) - qx);
            if (y0 > 0)     m = fminf(m, qy - (GLO + (float)y0 * GH));
            if (y1 < G - 1) m = fminf(m, (GLO + (float)(y1 + 1) * GH) - qy);
            if (z0 > 0)     m = fminf(m, qz - (GLO + (float)z0 * GH));
            if (z1 < G - 1) m = fminf(m, (GLO + (float)(z1 + 1) * GH) - qz);
            m = fmaxf(m, 0.0f);

            if (!(wbest <= m * m) &&
                !(x0 == 0 && y0 == 0 && z0 == 0 &&
                  x1 == G - 1 && y1 == G - 1 && z1 == G - 1)) {
                // ---- Rare escalation: incremental rings from r=2 ----
                int px0 = x0, px1 = x1, py0 = y0, py1 = y1, pz0 = z0, pz1 = z1;
                for (int r = 2; r < G; r++) {
                    const int bx0 = max(hx - r, 0), bx1 = min(hx + r, G - 1);
                    const int by0 = max(hy - r, 0), by1 = min(hy + r, G - 1);
                    const int bz0 = max(hz - r, 0), bz1 = min(hz + r, G - 1);
                    for (int cz = bz0; cz <= bz1; cz++) {
                        const bool zin = (cz >= pz0 && cz <= pz1);
                        for (int cy = by0; cy <= by1; cy++) {
                            const int rowbase = cbase + (cz * G + cy) * G;
                            const bool in_prev = zin && cy >= py0 && cy <= py1;
                            int sa, sb, sc, sd;
                            if (!in_prev) { sa = bx0; sb = bx1; sc = 1; sd = 0; }
                            else { sa = bx0; sb = px0 - 1; sc = px1 + 1; sd = bx1; }
                            if (sa <= sb) {
                                int s0 = g_cellstart[rowbase + sa];
                                int e0 = g_cellstart[rowbase + sb + 1];
                                for (int i = s0 + lane; i < e0; i += 32) {
                                    float4 tp = g_tsorted[i];
                                    float ddx = qx - tp.x;
                                    float ddy = qy - tp.y;
                                    float ddz = qz - tp.z;
                                    lbest = fminf(lbest,
                                        fmaf(ddx, ddx, fmaf(ddy, ddy, ddz * ddz)));
                                }
                            }
                            if (sc <= sd) {
                                int s0 = g_cellstart[rowbase + sc];
                                int e0 = g_cellstart[rowbase + sd + 1];
                                for (int i = s0 + lane; i < e0; i += 32) {
                                    float4 tp = g_tsorted[i];
                                    float ddx = qx - tp.x;
                                    float ddy = qy - tp.y;
                                    float ddz = qz - tp.z;
                                    lbest = fminf(lbest,
                                        fmaf(ddx, ddx, fmaf(ddy, ddy, ddz * ddz)));
                                }
                            }
                        }
                    }
                    float wm = lbest;
#pragma unroll
                    for (int o = 16; o > 0; o >>= 1)
                        wm = fminf(wm, __shfl_xor_sync(FULL, wm, o));
                    wbest = wm;

                    float mm = INF;
                    if (bx0 > 0)     mm = fminf(mm, qx - (GLO + (float)bx0 * GH));
                    if (bx1 < G - 1) mm = fminf(mm, (GLO + (float)(bx1 + 1) * GH) - qx);
                    if (by0 > 0)     mm = fminf(mm, qy - (GLO + (float)by0 * GH));
                    if (by1 < G - 1) mm = fminf(mm, (GLO + (float)(by1 + 1) * GH) - qy);
                    if (bz0 > 0)     mm = fminf(mm, qz - (GLO + (float)bz0 * GH));
                    if (bz1 < G - 1) mm = fminf(mm, (GLO + (float)(bz1 + 1) * GH) - qz);
                    mm = fmaxf(mm, 0.0f);
                    if (wbest <= mm * mm) break;
                    if (bx0 == 0 && by0 == 0 && bz0 == 0 &&
                        bx1 == G - 1 && by1 == G - 1 && bz1 == G - 1) break;
                    px0 = bx0; px1 = bx1; py0 = by0; py1 = by1; pz0 = bz0; pz1 = bz1;
                }
            }
            if (lane == 0) acc += sqrtf(fmaxf(wbest, 0.0f));
        }
    }

    // Block-level sum of per-warp accumulators, then one atomicAdd per block.
    if (lane == 0) fw[wid] = acc;
    __syncthreads();
    if (threadIdx.x == 0) {
        float s = 0.0f;
#pragma unroll
        for (int w = 0; w < WPB; w++) s += fw[w];
        atomicAdd(out, s * (1.0f / (float)NQ));
    }
}

extern "C" void kernel_launch(void* const* d_in, const int* in_sizes, int n_in,
                              void* d_out, int out_size) {
    const float* pred = (const float*)d_in[0];
    const float* target = (const float*)d_in[1];
    const int* idx = (const int*)d_in[2];
    float* out = (float*)d_out;

    fused_chamfer_kernel<<<NBLK, TPB>>>(target, pred, idx, out);
}

// round 12
// speedup vs baseline: 1.8549x; 1.4719x over previous
#include <cuda_runtime.h>
#include <cuda_bf16.h>

// Problem constants (fixed by the reference setup_inputs)
#define BB 2
#define NN 8192
#define MM 32768
#define SS 4096
#define NQ (BB * SS)          // 8192 queries
#define NT (BB * MM)          // 65536 targets

// Spatial grid: 32^3 cells per batch over [-4.8, 4.8], h = 0.3
#define G 32
#define GLO (-4.8f)
#define GH 0.3f
#define GINVH 3.33333333f
#define CELLS_PER_B (G * G * G)       // 32768
#define NC (BB * CELLS_PER_B)         // 65536

// Single fused kernel: 148 blocks (one per SM, co-resident) x 1024 threads
#define NBLK 148
#define TPB 1024
#define NTHREADS (NBLK * TPB)
#define WPB (TPB / 32)                 // 32 warps per block

// Scan decomposition: 64 scan-blocks x 1024 cells (1 cell per thread)
#define SCB 64
#define CPB (NC / SCB)                 // 1024

#define QCHUNK 2                       // queries stolen per warp grab
#define FULL 0xFFFFFFFFu

// Device scratch (no allocations allowed). All counters self-restore each call.
__device__ float4 g_target4[NT];     // (x, y, z, cell-id-as-int-bits)
__device__ float4 g_tsorted[NT];     // cell-sorted targets
__device__ float4 g_pred4[NQ];       // gathered query points
__device__ int    g_count[NC];
__device__ int    g_cellstart[NC + 1];
__device__ int    g_bsum[SCB];
__device__ int    g_qnext;                  // work-steal cursor (reset per launch)
__device__ int           g_bar_count;       // resets to 0 at every barrier
__device__ volatile int  g_bar_gen;         // monotonic across barriers/replays

__device__ __forceinline__ void grid_barrier() {
    __syncthreads();
    if (threadIdx.x == 0) {
        __threadfence();
        int gen = g_bar_gen;
        int arrived = atomicAdd(&g_bar_count, 1);
        if (arrived == NBLK - 1) {
            g_bar_count = 0;
            __threadfence();
            g_bar_gen = gen + 1;
        } else {
            while (g_bar_gen == gen) { }
        }
        __threadfence();
    }
    __syncthreads();
}

__device__ __forceinline__ int cell_coord(float v) {
    int c = (int)((v - GLO) * GINVH);
    return min(max(c, 0), G - 1);
}

// idx is int32 on device (JAX x64-disabled coerces int64 -> int32).
__global__ void __launch_bounds__(TPB) fused_chamfer_kernel(
    const float* __restrict__ target,
    const float* __restrict__ pred,
    const int* __restrict__ idx,
    float* __restrict__ out
) {
    __shared__ int   iw[WPB];
    __shared__ int   sh_boff;
    __shared__ float fw[WPB];

    const int tid = blockIdx.x * TPB + threadIdx.x;
    const int lane = threadIdx.x & 31;
    const int wid = threadIdx.x >> 5;

    // ---- Phase 0: zero counts/out/cursor, gather query points ----
    if (tid < NC) g_count[tid] = 0;
    if (tid < NQ) {
        int b = tid / SS;
        int s = tid % SS;
        int j = min(max(idx[s], 0), NN - 1);
        const float* p = pred + ((long long)b * NN + j) * 3;
        g_pred4[tid] = make_float4(p[0], p[1], p[2], 0.0f);
    }
    if (tid == 0) { out[0] = 0.0f; g_qnext = 0; }
    grid_barrier();

    // ---- Phase 1: histogram targets into cells ----
    if (tid < NT) {
        int i = tid;
        float x = target[3 * i + 0];
        float y = target[3 * i + 1];
        float z = target[3 * i + 2];
        int b = i / MM;
        int cell = b * CELLS_PER_B +
                   ((cell_coord(z) * G + cell_coord(y)) * G + cell_coord(x));
        g_target4[i] = make_float4(x, y, z, __int_as_float(cell));
        atomicAdd(&g_count[cell], 1);
    }
    grid_barrier();

    // ---- Phase 2a: per-scan-block totals (blocks 0..63, 1 cell/thread) ----
    if (blockIdx.x < SCB) {
        int s = g_count[blockIdx.x * CPB + threadIdx.x];
#pragma unroll
        for (int o = 16; o > 0; o >>= 1) s += __shfl_down_sync(FULL, s, o);
        if (lane == 0) iw[wid] = s;
        __syncthreads();
        if (threadIdx.x == 0) {
            int t = 0;
#pragma unroll
            for (int w = 0; w < WPB; w++) t += iw[w];
            g_bsum[blockIdx.x] = t;
        }
    }
    grid_barrier();

    // ---- Phase 2b+c: block prefix over g_bsum + local scan -> g_cellstart ----
    if (blockIdx.x < SCB) {
        // Warp 0: sum of g_bsum[0 .. blockIdx.x-1]
        if (wid == 0) {
            int a = (lane < blockIdx.x) ? g_bsum[lane] : 0;
            int b = (lane + 32 < blockIdx.x) ? g_bsum[lane + 32] : 0;
            int s = a + b;
#pragma unroll
            for (int o = 16; o > 0; o >>= 1) s += __shfl_down_sync(FULL, s, o);
            if (lane == 0) sh_boff = s;
        }
        int c = g_count[blockIdx.x * CPB + threadIdx.x];
        int incl = c;
#pragma unroll
        for (int o = 1; o < 32; o <<= 1) {
            int t = __shfl_up_sync(FULL, incl, o);
            if (lane >= o) incl += t;
        }
        if (lane == 31) iw[wid] = incl;
        __syncthreads();
        if (wid == 0) {
            int w = iw[lane];                  // WPB == 32: all lanes valid
#pragma unroll
            for (int o = 1; o < 32; o <<= 1) {
                int t = __shfl_up_sync(FULL, w, o);
                if (lane >= o) w += t;
            }
            iw[lane] = w;
        }
        __syncthreads();
        int pre = sh_boff + incl - c + (wid > 0 ? iw[wid - 1] : 0);
        g_cellstart[blockIdx.x * CPB + threadIdx.x] = pre;
    }
    if (tid == 0) g_cellstart[NC] = NT;
    grid_barrier();

    // ---- Phase 3: scatter into sorted order (consumes g_count back to 0) ----
    if (tid < NT) {
        float4 t = g_target4[tid];
        int cell = __float_as_int(t.w);
        int old = atomicAdd(&g_count[cell], -1);     // old in [1..count]
        g_tsorted[g_cellstart[cell] + old - 1] = t;
    }
    grid_barrier();

    // ---- Phase 4: warp-per-query NN ----
    // Fast path (r=1): one parallel 18-bound fetch + flat warp-parallel loop.
    // Escalation (rare): full-box rescan at growing r with LANE-PER-ROW
    // parallelism (each lane owns whole rows -> 32 independent load chains).
    const float INF = __int_as_float(0x7F800000);
    float acc = 0.0f;

    for (;;) {
        int base;
        if (lane == 0) base = atomicAdd(&g_qnext, QCHUNK);
        base = __shfl_sync(FULL, base, 0);
        if (base >= NQ) break;

        int qend = min(base + QCHUNK, NQ);
        for (int q = base; q < qend; q++) {
            float4 qp = g_pred4[q];
            const float qx = qp.x, qy = qp.y, qz = qp.z;
            const int hx = cell_coord(qx);
            const int hy = cell_coord(qy);
            const int hz = cell_coord(qz);
            const int cbase = (q / SS) * CELLS_PER_B;

            const int x0 = max(hx - 1, 0), x1 = min(hx + 1, G - 1);
            const int y0 = max(hy - 1, 0), y1 = min(hy + 1, G - 1);
            const int z0 = max(hz - 1, 0), z1 = min(hz + 1, G - 1);

            // Lanes 0-8: row starts; lanes 9-17: row ends. One round trip.
            int v = 0;
            {
                int i = (lane < 9) ? lane : lane - 9;
                if (lane < 18) {
                    int cz = hz + i / 3 - 1;
                    int cy = hy + i % 3 - 1;
                    if ((unsigned)cz < G && (unsigned)cy < G) {
                        int rowbase = cbase + (cz * G + cy) * G;
                        v = (lane < 9) ? g_cellstart[rowbase + x0]
                                       : g_cellstart[rowbase + x1 + 1];
                    }
                }
            }
            int S0 = __shfl_sync(FULL, v, 0), E0 = __shfl_sync(FULL, v, 9);
            int S1 = __shfl_sync(FULL, v, 1), E1 = __shfl_sync(FULL, v, 10);
            int S2 = __shfl_sync(FULL, v, 2), E2 = __shfl_sync(FULL, v, 11);
            int S3 = __shfl_sync(FULL, v, 3), E3 = __shfl_sync(FULL, v, 12);
            int S4 = __shfl_sync(FULL, v, 4), E4 = __shfl_sync(FULL, v, 13);
            int S5 = __shfl_sync(FULL, v, 5), E5 = __shfl_sync(FULL, v, 14);
            int S6 = __shfl_sync(FULL, v, 6), E6 = __shfl_sync(FULL, v, 15);
            int S7 = __shfl_sync(FULL, v, 7), E7 = __shfl_sync(FULL, v, 16);
            int S8 = __shfl_sync(FULL, v, 8), E8 = __shfl_sync(FULL, v, 17);
            int P1 = (E0 - S0);
            int P2 = P1 + (E1 - S1);
            int P3 = P2 + (E2 - S2);
            int P4 = P3 + (E3 - S3);
            int P5 = P4 + (E4 - S4);
            int P6 = P5 + (E5 - S5);
            int P7 = P6 + (E6 - S6);
            int P8 = P7 + (E7 - S7);
            int total = P8 + (E8 - S8);
            int D0 = S0;
            int D1 = S1 - P1;
            int D2 = S2 - P2;
            int D3 = S3 - P3;
            int D4 = S4 - P4;
            int D5 = S5 - P5;
            int D6 = S6 - P6;
            int D7 = S7 - P7;
            int D8 = S8 - P8;

            float lbest = INF;
#pragma unroll 4
            for (int t = lane; t < total; t += 32) {
                int d = D0;
                if (t >= P1) d = D1;
                if (t >= P2) d = D2;
                if (t >= P3) d = D3;
                if (t >= P4) d = D4;
                if (t >= P5) d = D5;
                if (t >= P6) d = D6;
                if (t >= P7) d = D7;
                if (t >= P8) d = D8;
                float4 tp = g_tsorted[d + t];
                float ddx = qx - tp.x;
                float ddy = qy - tp.y;
                float ddz = qz - tp.z;
                float d2 = fmaf(ddx, ddx, fmaf(ddy, ddy, ddz * ddz));
                lbest = fminf(lbest, d2);
            }
            float wbest = lbest;
#pragma unroll
            for (int o = 16; o > 0; o >>= 1)
                wbest = fminf(wbest, __shfl_xor_sync(FULL, wbest, o));

            // Exact stop bound for the r=1 box (clamped edges are open).
            float m = INF;
            if (x0 > 0)     m = fminf(m, qx - (GLO + (float)x0 * GH));
            if (x1 < G - 1) m = fminf(m, (GLO + (float)(x1 + 1) * GH) - qx);
            if (y0 > 0)     m = fminf(m, qy - (GLO + (float)y0 * GH));
            if (y1 < G - 1) m = fminf(m, (GLO + (float)(y1 + 1) * GH) - qy);
            if (z0 > 0)     m = fminf(m, qz - (GLO + (float)z0 * GH));
            if (z1 < G - 1) m = fminf(m, (GLO + (float)(z1 + 1) * GH) - qz);
            m = fmaxf(m, 0.0f);

            if (!(wbest <= m * m) &&
                !(x0 == 0 && y0 == 0 && z0 == 0 &&
                  x1 == G - 1 && y1 == G - 1 && z1 == G - 1)) {
                // ---- Rare escalation: full-box rescan, lane-per-row ----
                for (int r = 2; r < G; r++) {
                    const int bx0 = max(hx - r, 0), bx1 = min(hx + r, G - 1);
                    const int by0 = max(hy - r, 0), by1 = min(hy + r, G - 1);
                    const int bz0 = max(hz - r, 0), bz1 = min(hz + r, G - 1);
                    const int ny = by1 - by0 + 1;
                    const int nrows = (bz1 - bz0 + 1) * ny;

                    float lb = INF;
                    for (int rb = 0; rb < nrows; rb += 32) {
                        int rho = rb + lane;
                        int s0 = 0, e0 = 0;
                        if (rho < nrows) {
                            int cz = bz0 + rho / ny;
                            int cy = by0 + rho % ny;
                            int rowbase = cbase + (cz * G + cy) * G;
                            s0 = g_cellstart[rowbase + bx0];
                            e0 = g_cellstart[rowbase + bx1 + 1];
                        }
                        // Each lane walks its own row: 32 independent chains.
                        for (int i = s0; i < e0; i++) {
                            float4 tp = g_tsorted[i];
                            float ddx = qx - tp.x;
                            float ddy = qy - tp.y;
                            float ddz = qz - tp.z;
                            lb = fminf(lb,
                                fmaf(ddx, ddx, fmaf(ddy, ddy, ddz * ddz)));
                        }
                    }
                    float wm = lb;
#pragma unroll
                    for (int o = 16; o > 0; o >>= 1)
                        wm = fminf(wm, __shfl_xor_sync(FULL, wm, o));
                    wbest = wm;

                    float mm = INF;
                    if (bx0 > 0)     mm = fminf(mm, qx - (GLO + (float)bx0 * GH));
                    if (bx1 < G - 1) mm = fminf(mm, (GLO + (float)(bx1 + 1) * GH) - qx);
                    if (by0 > 0)     mm = fminf(mm, qy - (GLO + (float)by0 * GH));
                    if (by1 < G - 1) mm = fminf(mm, (GLO + (float)(by1 + 1) * GH) - qy);
                    if (bz0 > 0)     mm = fminf(mm, qz - (GLO + (float)bz0 * GH));
                    if (bz1 < G - 1) mm = fminf(mm, (GLO + (float)(bz1 + 1) * GH) - qz);
                    mm = fmaxf(mm, 0.0f);
                    if (wbest <= mm * mm) break;
                    if (bx0 == 0 && by0 == 0 && bz0 == 0 &&
                        bx1 == G - 1 && by1 == G - 1 && bz1 == G - 1) break;
                }
            }
            if (lane == 0) acc += sqrtf(fmaxf(wbest, 0.0f));
        }
    }

    // Block-level sum of per-warp accumulators, then one atomicAdd per block.
    if (lane == 0) fw[wid] = acc;
    __syncthreads();
    if (threadIdx.x == 0) {
        float s = 0.0f;
#pragma unroll
        for (int w = 0; w < WPB; w++) s += fw[w];
        atomicAdd(out, s * (1.0f / (float)NQ));
    }
}

extern "C" void kernel_launch(void* const* d_in, const int* in_sizes, int n_in,
                              void* d_out, int out_size) {
    const float* pred = (const float*)d_in[0];
    const float* target = (const float*)d_in[1];
    const int* idx = (const int*)d_in[2];
    float* out = (float*)d_out;

    fused_chamfer_kernel<<<NBLK, TPB>>>(target, pred, idx, out);
}

// round 14
// speedup vs baseline: 2.6105x; 1.4073x over previous
#include <cuda_runtime.h>
#include <cuda_bf16.h>

// Problem constants (fixed by the reference setup_inputs)
#define BB 2
#define NN 8192
#define MM 32768
#define SS 4096
#define NQ (BB * SS)          // 8192 queries
#define NT (BB * MM)          // 65536 targets

// Spatial grid: 32^3 cells per batch over [-4.8, 4.8], h = 0.3
#define G 32
#define GLO (-4.8f)
#define GH 0.3f
#define GINVH 3.33333333f
#define CELLS_PER_B (G * G * G)       // 32768
#define NC (BB * CELLS_PER_B)         // 65536

// Single fused kernel: 148 blocks (one per SM, co-resident) x 1024 threads
#define NBLK 148
#define TPB 1024
#define NTHREADS (NBLK * TPB)
#define WPB (TPB / 32)                 // 32 warps per block

// Scan decomposition: 64 scan-blocks x 1024 cells (1 cell per thread)
#define SCB 64
#define CPB (NC / SCB)                 // 1024

#define QCHUNK 2                       // queries stolen per warp grab
#define FULL 0xFFFFFFFFu

// Device scratch (no allocations allowed).
// g_count: zero at load; histogram +1/point, scatter -1/point -> restored to
// zero after every complete launch => no re-zeroing phase needed.
__device__ float4 g_target4[NT];     // (x, y, z, cell-id-as-int-bits)
__device__ float4 g_tsorted[NT];     // cell-sorted targets
__device__ float4 g_pred4[NQ];       // gathered query points
__device__ int    g_count[NC];
__device__ int    g_cellstart[NC + 1];
__device__ int    g_bsum[SCB];
__device__ int    g_qnext;                  // work-steal cursor (reset per launch)
__device__ int           g_bar_count;       // resets to 0 at every barrier
__device__ volatile int  g_bar_gen;         // monotonic across barriers/replays

__device__ __forceinline__ void grid_barrier() {
    __syncthreads();
    if (threadIdx.x == 0) {
        __threadfence();
        int gen = g_bar_gen;
        int arrived = atomicAdd(&g_bar_count, 1);
        if (arrived == NBLK - 1) {
            g_bar_count = 0;
            __threadfence();
            g_bar_gen = gen + 1;
        } else {
            while (g_bar_gen == gen) { }
        }
        __threadfence();
    }
    __syncthreads();
}

__device__ __forceinline__ int cell_coord(float v) {
    int c = (int)((v - GLO) * GINVH);
    return min(max(c, 0), G - 1);
}

// idx is int32 on device (JAX x64-disabled coerces int64 -> int32).
__global__ void __launch_bounds__(TPB) fused_chamfer_kernel(
    const float* __restrict__ target,
    const float* __restrict__ pred,
    const int* __restrict__ idx,
    float* __restrict__ out
) {
    __shared__ int   iw[WPB];
    __shared__ int   sh_boff;
    __shared__ float fw[WPB];

    const int tid = blockIdx.x * TPB + threadIdx.x;
    const int lane = threadIdx.x & 31;
    const int wid = threadIdx.x >> 5;

    // ---- Phase 1: histogram targets + gather queries + reset cursors ----
    if (tid < NT) {
        int i = tid;
        float x = target[3 * i + 0];
        float y = target[3 * i + 1];
        float z = target[3 * i + 2];
        int b = i / MM;
        int cell = b * CELLS_PER_B +
                   ((cell_coord(z) * G + cell_coord(y)) * G + cell_coord(x));
        g_target4[i] = make_float4(x, y, z, __int_as_float(cell));
        atomicAdd(&g_count[cell], 1);
    }
    if (tid < NQ) {
        int b = tid / SS;
        int s = tid % SS;
        int j = min(max(idx[s], 0), NN - 1);
        const float* p = pred + ((long long)b * NN + j) * 3;
        g_pred4[tid] = make_float4(p[0], p[1], p[2], 0.0f);
    }
    if (tid == 0) { out[0] = 0.0f; g_qnext = 0; }
    grid_barrier();

    // ---- Phase 2a: per-scan-block totals (blocks 0..63, 1 cell/thread) ----
    if (blockIdx.x < SCB) {
        int s = g_count[blockIdx.x * CPB + threadIdx.x];
#pragma unroll
        for (int o = 16; o > 0; o >>= 1) s += __shfl_down_sync(FULL, s, o);
        if (lane == 0) iw[wid] = s;
        __syncthreads();
        if (threadIdx.x == 0) {
            int t = 0;
#pragma unroll
            for (int w = 0; w < WPB; w++) t += iw[w];
            g_bsum[blockIdx.x] = t;
        }
    }
    grid_barrier();

    // ---- Phase 2b+c: block prefix over g_bsum + local scan -> g_cellstart ----
    if (blockIdx.x < SCB) {
        if (wid == 0) {
            int a = (lane < blockIdx.x) ? g_bsum[lane] : 0;
            int b = (lane + 32 < blockIdx.x) ? g_bsum[lane + 32] : 0;
            int s = a + b;
#pragma unroll
            for (int o = 16; o > 0; o >>= 1) s += __shfl_down_sync(FULL, s, o);
            if (lane == 0) sh_boff = s;
        }
        int c = g_count[blockIdx.x * CPB + threadIdx.x];
        int incl = c;
#pragma unroll
        for (int o = 1; o < 32; o <<= 1) {
            int t = __shfl_up_sync(FULL, incl, o);
            if (lane >= o) incl += t;
        }
        if (lane == 31) iw[wid] = incl;
        __syncthreads();
        if (wid == 0) {
            int w = iw[lane];                  // WPB == 32: all lanes valid
#pragma unroll
            for (int o = 1; o < 32; o <<= 1) {
                int t = __shfl_up_sync(FULL, w, o);
                if (lane >= o) w += t;
            }
            iw[lane] = w;
        }
        __syncthreads();
        int pre = sh_boff + incl - c + (wid > 0 ? iw[wid - 1] : 0);
        g_cellstart[blockIdx.x * CPB + threadIdx.x] = pre;
    }
    if (tid == 0) g_cellstart[NC] = NT;
    grid_barrier();

    // ---- Phase 3: scatter into sorted order (consumes g_count back to 0) ----
    if (tid < NT) {
        float4 t = g_target4[tid];
        int cell = __float_as_int(t.w);
        int old = atomicAdd(&g_count[cell], -1);     // old in [1..count]
        g_tsorted[g_cellstart[cell] + old - 1] = t;
    }
    grid_barrier();

    // ---- Phase 4: warp-per-query NN ----
    // Fast path: nearest-corner 2x2x2 cell box (4 row segments, 8 bounds in
    // one round trip, 3-SEL flat loop). Exact stop: warp-min d^2 <= squared
    // real distance to box boundary (open faces at domain edge).
    // Escalation (rare): lane-per-row full-box rescan from r=1 around home.
    const float INF = __int_as_float(0x7F800000);
    float acc = 0.0f;

    for (;;) {
        int base;
        if (lane == 0) base = atomicAdd(&g_qnext, QCHUNK);
        base = __shfl_sync(FULL, base, 0);
        if (base >= NQ) break;

        int qend = min(base + QCHUNK, NQ);
        for (int q = base; q < qend; q++) {
            float4 qp = g_pred4[q];
            const float qx = qp.x, qy = qp.y, qz = qp.z;
            const int cbase = (q / SS) * CELLS_PER_B;

            // Nearest grid corner -> 2x2x2 box [c0, c0+1] per dim
            int cx0 = (int)floorf((qx - GLO) * GINVH + 0.5f) - 1;
            int cy0 = (int)floorf((qy - GLO) * GINVH + 0.5f) - 1;
            int cz0 = (int)floorf((qz - GLO) * GINVH + 0.5f) - 1;
            cx0 = min(max(cx0, 0), G - 2);
            cy0 = min(max(cy0, 0), G - 2);
            cz0 = min(max(cz0, 0), G - 2);

            // Lanes 0-3: row starts; lanes 4-7: row ends. One round trip.
            int v = 0;
            if (lane < 8) {
                int i = lane & 3;
                int cz = cz0 + (i >> 1);
                int cy = cy0 + (i & 1);
                int rowbase = cbase + (cz * G + cy) * G;
                v = (lane < 4) ? g_cellstart[rowbase + cx0]
                               : g_cellstart[rowbase + cx0 + 2];
            }
            int S0 = __shfl_sync(FULL, v, 0), E0 = __shfl_sync(FULL, v, 4);
            int S1 = __shfl_sync(FULL, v, 1), E1 = __shfl_sync(FULL, v, 5);
            int S2 = __shfl_sync(FULL, v, 2), E2 = __shfl_sync(FULL, v, 6);
            int S3 = __shfl_sync(FULL, v, 3), E3 = __shfl_sync(FULL, v, 7);
            int P1 = (E0 - S0);
            int P2 = P1 + (E1 - S1);
            int P3 = P2 + (E2 - S2);
            int total = P3 + (E3 - S3);
            int D0 = S0;
            int D1 = S1 - P1;
            int D2 = S2 - P2;
            int D3 = S3 - P3;

            float lbest = INF;
#pragma unroll 4
            for (int t = lane; t < total; t += 32) {
                int d = D0;
                if (t >= P1) d = D1;
                if (t >= P2) d = D2;
                if (t >= P3) d = D3;
                float4 tp = g_tsorted[d + t];
                float ddx = qx - tp.x;
                float ddy = qy - tp.y;
                float ddz = qz - tp.z;
                float d2 = fmaf(ddx, ddx, fmaf(ddy, ddy, ddz * ddz));
                lbest = fminf(lbest, d2);
            }
            float wbest = lbest;
#pragma unroll
            for (int o = 16; o > 0; o >>= 1)
                wbest = fminf(wbest, __shfl_xor_sync(FULL, wbest, o));

            // Exact stop bound: distance to box faces (domain-edge faces open)
            float m = INF;
            if (cx0 > 0)     m = fminf(m, qx - (GLO + (float)cx0 * GH));
            if (cx0 + 2 < G) m = fminf(m, (GLO + (float)(cx0 + 2) * GH) - qx);
            if (cy0 > 0)     m = fminf(m, qy - (GLO + (float)cy0 * GH));
            if (cy0 + 2 < G) m = fminf(m, (GLO + (float)(cy0 + 2) * GH) - qy);
            if (cz0 > 0)     m = fminf(m, qz - (GLO + (float)cz0 * GH));
            if (cz0 + 2 < G) m = fminf(m, (GLO + (float)(cz0 + 2) * GH) - qz);
            m = fmaxf(m, 0.0f);

            if (!(wbest <= m * m)) {
                // ---- Escalation: full-box rescan from r=1, lane-per-row ----
                const int hx = cell_coord(qx);
                const int hy = cell_coord(qy);
                const int hz = cell_coord(qz);
                for (int r = 1; r < G; r++) {
                    const int bx0 = max(hx - r, 0), bx1 = min(hx + r, G - 1);
                    const int by0 = max(hy - r, 0), by1 = min(hy + r, G - 1);
                    const int bz0 = max(hz - r, 0), bz1 = min(hz + r, G - 1);
                    const int ny = by1 - by0 + 1;
                    const int nrows = (bz1 - bz0 + 1) * ny;

                    float lb = INF;
                    for (int rb = 0; rb < nrows; rb += 32) {
                        int rho = rb + lane;
                        int s0 = 0, e0 = 0;
                        if (rho < nrows) {
                            int cz = bz0 + rho / ny;
                            int cy = by0 + rho % ny;
                            int rowbase = cbase + (cz * G + cy) * G;
                            s0 = g_cellstart[rowbase + bx0];
                            e0 = g_cellstart[rowbase + bx1 + 1];
                        }
                        // Each lane walks its own row: 32 independent chains.
                        for (int i = s0; i < e0; i++) {
                            float4 tp = g_tsorted[i];
                            float ddx = qx - tp.x;
                            float ddy = qy - tp.y;
                            float ddz = qz - tp.z;
                            lb = fminf(lb,
                                fmaf(ddx, ddx, fmaf(ddy, ddy, ddz * ddz)));
                        }
                    }
                    float wm = lb;
#pragma unroll
                    for (int o = 16; o > 0; o >>= 1)
                        wm = fminf(wm, __shfl_xor_sync(FULL, wm, o));
                    wbest = fminf(wbest, wm);

                    float mm = INF;
                    if (bx0 > 0)     mm = fminf(mm, qx - (GLO + (float)bx0 * GH));
                    if (bx1 < G - 1) mm = fminf(mm, (GLO + (float)(bx1 + 1) * GH) - qx);
                    if (by0 > 0)     mm = fminf(mm, qy - (GLO + (float)by0 * GH));
                    if (by1 < G - 1) mm = fminf(mm, (GLO + (float)(by1 + 1) * GH) - qy);
                    if (bz0 > 0)     mm = fminf(mm, qz - (GLO + (float)bz0 * GH));
                    if (bz1 < G - 1) mm = fminf(mm, (GLO + (float)(bz1 + 1) * GH) - qz);
                    mm = fmaxf(mm, 0.0f);
                    if (wbest <= mm * mm) break;
                    if (bx0 == 0 && by0 == 0 && bz0 == 0 &&
                        bx1 == G - 1 && by1 == G - 1 && bz1 == G - 1) break;
                }
            }
            if (lane == 0) acc += sqrtf(fmaxf(wbest, 0.0f));
        }
    }

    // Block-level sum of per-warp accumulators, then one atomicAdd per block.
    if (lane == 0) fw[wid] = acc;
    __syncthreads();
    if (threadIdx.x == 0) {
        float s = 0.0f;
#pragma unroll
        for (int w = 0; w < WPB; w++) s += fw[w];
        atomicAdd(out, s * (1.0f / (float)NQ));
    }
}

extern "C" void kernel_launch(void* const* d_in, const int* in_sizes, int n_in,
                              void* d_out, int out_size) {
    const float* pred = (const float*)d_in[0];
    const float* target = (const float*)d_in[1];
    const int* idx = (const int*)d_in[2];
    float* out = (float*)d_out;

    fused_chamfer_kernel<<<NBLK, TPB>>>(target, pred, idx, out);
}